// round 11
// baseline (speedup 1.0000x reference)
#include <cuda_runtime.h>
#include <math.h>

// ---------------------------------------------------------------------------
// SoftLabelLoss: loss = max( (1/B) * sum_i [ e[t_i] - dot(soft[t_i], x_i) + lse(x_i) ], 0 )
// v11 = v10 (unroll-4 register pipeline + batched smem lse) with:
//   - 32-bit indexing (register diet, kill spills)
//   - targets window double-buffer (no boundary stall)
//   - t-shuffle pipelined one row ahead (weight LDS off the critical path)
// ---------------------------------------------------------------------------

#define FXSCALE 4294967296.0   // 2^32

__device__ unsigned long long g_sum  = 0ULL;
__device__ unsigned int       g_done = 0u;

__device__ __forceinline__ float warp_sum_f32(float v) {
    #pragma unroll
    for (int o = 16; o; o >>= 1) v += __shfl_xor_sync(0xffffffffu, v, o);
    return v;
}

// --- deterministic fixed-point finalize -------------------------------------------
__device__ __forceinline__ void block_finalize(float acc, int lane, int warp,
                                               double* s_w, float* out, int B) {
    double d = (double)acc;
    #pragma unroll
    for (int o = 16; o; o >>= 1) d += __shfl_xor_sync(0xffffffffu, d, o);
    if (lane == 0) s_w[warp] = d;
    __syncthreads();
    if (warp == 0) {
        int nw = (blockDim.x + 31) >> 5;
        double v = (lane < nw) ? s_w[lane] : 0.0;
        #pragma unroll
        for (int o = 16; o; o >>= 1) v += __shfl_xor_sync(0xffffffffu, v, o);
        if (lane == 0) {
            long long q = __double2ll_rn(v * FXSCALE);
            atomicAdd(&g_sum, (unsigned long long)q);
            __threadfence();
            unsigned int tk = atomicAdd(&g_done, 1u);
            if (tk == gridDim.x - 1) {
                unsigned long long raw = atomicAdd(&g_sum, 0ULL);
                double loss = ((double)(long long)raw / FXSCALE) / (double)B;
                out[0] = (float)(loss > 0.0 ? loss : 0.0);
                g_sum  = 0ULL;
                g_done = 0u;
                __threadfence();
            }
        }
    }
}

// --- shared f32 table build (warp-cooperative) --------------------------------------
__device__ __forceinline__ void build_table(const float* __restrict__ sim,
                                            float* s_soft, float* s_ent,
                                            int C, int lane, int warp) {
    for (int t = warp; t < C; t += 32) {
        const float* srow = sim + (size_t)t * C;
        float s = 0.0f;
        for (int c = lane; c < C; c += 32) {
            float v = __ldg(srow + c);
            s_soft[t * C + c] = v;
            s += v;
        }
        s = warp_sum_f32(s);
        float inv = 0.2f / s;
        float p = 0.0f;
        for (int c = lane; c < C; c += 32) {
            float soft = s_soft[t * C + c] * inv + (c == t ? 0.8f : 0.0f);
            s_soft[t * C + c] = soft;
            p += (soft > 0.0f) ? soft * __logf(soft) : 0.0f;
        }
        p = warp_sum_f32(p);
        if (lane == 0) s_ent[t] = p;
    }
}

// --- v11 main kernel, compile-time C (C even, 128 < C <= 172) ------------------------
template<int C>
__global__ __launch_bounds__(1024, 1)
void slloss_v11(const float* __restrict__ logits,
                const int*   __restrict__ targets,
                const float* __restrict__ sim,
                float* __restrict__ out, int B) {
    constexpr int C2   = C / 2;         // float2 per row (85)
    constexpr int RSTR = 36;            // se-partial row stride (floats)
    static_assert((C & 1) == 0 && C2 > 64 && C2 <= 86, "tuned for 128<C<=172");

    extern __shared__ __align__(16) unsigned char smraw[];
    double* s_w    = (double*)smraw;                              // 256 B
    float*  s_ent  = (float*)(smraw + 256);                       // C floats (pad 688)
    float*  s_soft = (float*)(smraw + 256 + 688);                 // C*C floats
    float*  s_red  = (float*)(smraw + 256 + 688 + C * C * 4);     // 32*16*RSTR floats

    const int lane = threadIdx.x & 31;
    const int warp = threadIdx.x >> 5;

    build_table(sim, s_soft, s_ent, C, lane, warp);
    __syncthreads();

    const int NW = gridDim.x * 32;
    const int gw = blockIdx.x * 32 + warp;

    int per = (int)((((long long)B + NW - 1) / NW + 15) & ~15LL);   // mult of 16
    int r0  = gw * per;      if (r0 > B) r0 = B;
    int r1  = r0 + per;      if (r1 > B) r1 = B;
    const int n   = r1 - r0;
    const int n16 = n & ~15;

    const bool act2 = lane < (C2 - 64);       // partial third chunk (lane < 21)
    float* red = s_red + warp * (16 * RSTR);

    float accD = 0.0f;   // -dot partials (all lanes)
    float accL = 0.0f;   // ent + log(se) (lanes 0..15)

    if (n16 >= 16) {
        const float2* p = (const float2*)logits + (size_t)r0 * C2;
        const int* tg = targets + r0;

        // targets window double-buffer (32 rows each)
        int t32  = (lane      < n) ? __ldg(tg + lane)      : -1;
        int t32n = (lane + 32 < n) ? __ldg(tg + 32 + lane) : -1;

        float2 b0[3], b1[3], b2[3], b3[3];
        #define LD3(BUF, D)                                       \
            BUF[0] = __ldcs(p + (D) * C2 + lane);                 \
            BUF[1] = __ldcs(p + (D) * C2 + 32 + lane);            \
            if (act2) BUF[2] = __ldcs(p + (D) * C2 + 64 + lane);
        LD3(b0, 0) LD3(b1, 1) LD3(b2, 2) LD3(b3, 3)

        int tcur = __shfl_sync(0xffffffffu, t32, 0);   // t for row 0

        for (int i = 0; i < n16; i += 16) {
            // window rotation: consume current, prefetch next (32 rows ahead)
            if ((i & 31) == 0 && i > 0) {
                t32  = t32n;
                t32n = (i + 32 + lane < n) ? __ldg(tg + i + 32 + lane) : -1;
            }
            const int sidx = i & 31;                   // 0 or 16

            #pragma unroll
            for (int rr = 0; rr < 16; rr += 4) {
                const bool more = (i + rr + 4) < n16;

                #define DO_ROW(BUF, D)                                              \
                {                                                                   \
                    const int t  = tcur;                                            \
                    const int tw = (t >= 0) ? t : 0;                                \
                    const float2* sw = (const float2*)(s_soft + tw * C);            \
                    float2 w0 = sw[lane];                                           \
                    float2 w1 = sw[lane + 32];                                      \
                    float2 w2;                                                      \
                    if (act2) w2 = sw[lane + 64];                                   \
                    /* pipeline next row's target (overlaps LDS latency) */         \
                    {                                                               \
                        int nidx = (sidx + rr + (D) + 1) & 31;                      \
                        int src  = nidx ? t32 : t32n;                               \
                        tcur = __shfl_sync(0xffffffffu, src, nidx);                 \
                    }                                                               \
                    float2 x0 = BUF[0], x1 = BUF[1], x2 = BUF[2];                   \
                    if (more) { LD3(BUF, (D) + 4) }                                 \
                    float seA = __expf(x0.x) + __expf(x0.y);                        \
                    float seB = __expf(x1.x) + __expf(x1.y);                        \
                    float dt = 0.0f;                                                \
                    dt = fmaf(w0.x, x0.x, dt); dt = fmaf(w0.y, x0.y, dt);           \
                    dt = fmaf(w1.x, x1.x, dt); dt = fmaf(w1.y, x1.y, dt);           \
                    if (act2) {                                                     \
                        seA += __expf(x2.x) + __expf(x2.y);                         \
                        dt = fmaf(w2.x, x2.x, dt); dt = fmaf(w2.y, x2.y, dt);       \
                    }                                                               \
                    red[(rr + (D)) * RSTR + lane] = seA + seB;                      \
                    if (t >= 0) accD -= dt;                                         \
                }

                DO_ROW(b0, 0)
                DO_ROW(b1, 1)
                DO_ROW(b2, 2)
                DO_ROW(b3, 3)
                #undef DO_ROW

                p += 4 * C2;
            }

            // batched lse: lanes 0..15 each own one row of this 16-row group
            __syncwarp();
            float sum = 0.0f;
            if (lane < 16) {
                const float4* q = (const float4*)(red + lane * RSTR);
                #pragma unroll
                for (int k = 0; k < 8; k++) {
                    float4 v = q[k];
                    sum += (v.x + v.y) + (v.z + v.w);
                }
            }
            int tr = __shfl_sync(0xffffffffu, t32, (sidx + lane) & 31);
            if (lane < 16 && tr >= 0) accL += s_ent[tr] + __logf(sum);
            __syncwarp();
        }
        #undef LD3
    }

    // scalar tail (<16 rows; empty when per-warp ranges are 16-multiples)
    for (int i = n16; i < n; i++) {
        int t = __ldg(targets + r0 + i);
        const float* lg = logits + (size_t)(r0 + i) * C;
        const float* sw = s_soft + ((t >= 0) ? t : 0) * C;
        float se = 0.f, dt = 0.f;
        for (int c = lane; c < C; c += 32) {
            float x = __ldg(lg + c);
            se += __expf(x);
            dt = fmaf(sw[c], x, dt);
        }
        se = warp_sum_f32(se);
        if (t >= 0) {
            accD -= dt;
            if (lane == 0) accL += s_ent[t] + __logf(se);
        }
    }

    block_finalize(accD + accL, lane, warp, s_w, out, B);
}

// --- generic fallback (any C, f32 table) ---------------------------------------------
__global__ __launch_bounds__(1024, 1)
void slloss_fused_gen(const float* __restrict__ logits,
                      const int*   __restrict__ targets,
                      const float* __restrict__ sim,
                      float* __restrict__ out,
                      int B, int C) {
    extern __shared__ float smemf[];
    float*  s_soft = smemf;
    float*  s_ent  = smemf + C * C;
    double* s_w    = (double*)(smemf + C * C + ((C + 1) & ~1));

    const int tid = threadIdx.x, lane = tid & 31, warp = tid >> 5;
    build_table(sim, s_soft, s_ent, C, lane, warp);
    __syncthreads();

    const int NW = gridDim.x * 32;
    const int gw = blockIdx.x * 32 + warp;
    long long per = ((long long)B + NW - 1) / NW;
    long long r0 = (long long)gw * per; if (r0 > B) r0 = B;
    long long r1 = r0 + per;            if (r1 > B) r1 = B;

    float acc = 0.0f;
    for (long long row = r0; row < r1; row++) {
        int t = __ldg(&targets[row]);
        if (t < 0) continue;
        const float* lg = logits + (size_t)row * C;
        const float* sw = s_soft + t * C;
        float se = 0.f, dt = 0.f;
        for (int c = lane; c < C; c += 32) {
            float x = __ldg(lg + c);
            se += __expf(x);
            dt = fmaf(sw[c], x, dt);
        }
        se = warp_sum_f32(se);
        acc -= dt;
        if (lane == 0) acc += s_ent[t] + __logf(se);
    }
    block_finalize(acc, lane, warp, s_w, out, B);
}

extern "C" void kernel_launch(void* const* d_in, const int* in_sizes, int n_in,
                              void* d_out, int out_size) {
    const float* logits  = (const float*)d_in[0];
    const int*   targets = (const int*)  d_in[1];
    const float* sim     = (const float*)d_in[2];
    float*       out     = (float*)d_out;

    int B = in_sizes[1];
    int C = in_sizes[0] / B;

    int nsm = 148;
    cudaDeviceGetAttribute(&nsm, cudaDevAttrMultiProcessorCount, 0);

    if (C == 170) {
        constexpr int Cc = 170;
        size_t smem = 256 + 688 + (size_t)Cc * Cc * 4 + (size_t)32 * 16 * 36 * 4;
        cudaFuncSetAttribute(slloss_v11<Cc>, cudaFuncAttributeMaxDynamicSharedMemorySize, (int)smem);
        slloss_v11<Cc><<<nsm, 1024, smem>>>(logits, targets, sim, out, B);
    } else {
        size_t smem = (size_t)(C * C + ((C + 1) & ~1)) * sizeof(float) + 32 * sizeof(double);
        cudaFuncSetAttribute(slloss_fused_gen, cudaFuncAttributeMaxDynamicSharedMemorySize, (int)smem);
        slloss_fused_gen<<<nsm, 1024, smem>>>(logits, targets, sim, out, B, C);
    }
}